// round 7
// baseline (speedup 1.0000x reference)
#include <cuda_runtime.h>
#include <math.h>
#include <stdint.h>

#define BATCH 4
#define CH    512
#define LEN   2048

__device__ float g_yq[BATCH*CH*LEN];
__device__ float g_yk[BATCH*CH*LEN];
__device__ float g_yv[BATCH*CH*LEN];
__device__ float g_z [BATCH*CH*LEN];

// ---- tf32 helpers -----------------------------------------------------------
__device__ __forceinline__ uint32_t tf32_rna(float a) {
    uint32_t r; asm("cvt.rna.tf32.f32 %0, %1;" : "=r"(r) : "f"(a)); return r;
}
__device__ __forceinline__ void split_tf32(float a, uint32_t& hi, uint32_t& lo) {
    hi = tf32_rna(a);
    lo = tf32_rna(a - __uint_as_float(hi));
}
__device__ __forceinline__ void mma_tf32(float4& d, const uint32_t* a,
                                         uint32_t b0, uint32_t b1) {
    asm volatile(
        "mma.sync.aligned.m16n8k8.row.col.f32.tf32.tf32.f32 "
        "{%0,%1,%2,%3},{%4,%5,%6,%7},{%8,%9},{%0,%1,%2,%3};"
        : "+f"(d.x), "+f"(d.y), "+f"(d.z), "+f"(d.w)
        : "r"(a[0]), "r"(a[1]), "r"(a[2]), "r"(a[3]), "r"(b0), "r"(b1));
}

// ---------------------------------------------------------------------------
// Conv1d (k=3, 'same') on tensor cores, double-buffered smem pipeline.
// W always split (hi/lo); X split only for the fc conv (SPLITX).
// Block tile 64co x 128pos, 256 threads = 8 warps, warp tile 16co x 64pos.
// Per chunk (8 ci): LDG next -> 48 (or 72) MMAs on buf -> cvt+STS next -> sync.
// ---------------------------------------------------------------------------
#define WS_PITCH 72    // 72 % 32 == 8 -> A-frag reads conflict-free
#define XS_PITCH 136   // 136 % 32 == 8 -> B-frag reads conflict-free

template<bool SPLITX>
__device__ __forceinline__
void conv_body(const float* __restrict__ x, const float* __restrict__ w,
               const float* __restrict__ bias, float* __restrict__ y,
               int b, int co0, int l0)
{
    __shared__ uint32_t Wh[2][24][WS_PITCH], Wl[2][24][WS_PITCH];
    __shared__ uint32_t Xh[2][8][XS_PITCH];
    __shared__ uint32_t Xl[2][8][XS_PITCH];   // used only if SPLITX

    const int tid  = threadIdx.x;
    const int lane = tid & 31;
    const int wid  = tid >> 5;
    const int g    = lane >> 2;       // 0..7
    const int tg   = lane & 3;        // 0..3
    const int wco  = (wid & 3) << 4;  // 0,16,32,48
    const int wpos = (wid >> 2) << 6; // 0,64
    const float* xb = x + (size_t)b * (CH * LEN);

    float4 acc[8];
    #pragma unroll
    for (int i = 0; i < 8; i++) acc[i] = make_float4(0.f, 0.f, 0.f, 0.f);

    // staging roles
    const int xr     = tid >> 5;        // X row 0..7 (one row per warp)
    const int wco_ld = tid >> 2;        // 0..63
    const int wr_ld  = (tid & 3) * 6;   // 0,6,12,18

    float rx[5], rw[6];

    // ---- prefetch + stage chunk 0 into buf 0 ----
    {
        const float* xrow = xb + (size_t)xr * LEN + (l0 - 1);
        #pragma unroll
        for (int i = 0; i < 5; i++) {
            int c = lane + (i << 5);
            int gl = l0 - 1 + c;
            rx[i] = (c < 130 && gl >= 0 && gl < LEN) ? xrow[c] : 0.f;
        }
        const float* wp = w + (size_t)(co0 + wco_ld) * (CH * 3) + wr_ld;
        #pragma unroll
        for (int i = 0; i < 6; i++) rw[i] = wp[i];

        #pragma unroll
        for (int i = 0; i < 5; i++) {
            int c = lane + (i << 5);
            if (c < 130) {
                if (SPLITX) {
                    uint32_t hi, lo; split_tf32(rx[i], hi, lo);
                    Xh[0][xr][c] = hi; Xl[0][xr][c] = lo;
                } else {
                    Xh[0][xr][c] = tf32_rna(rx[i]);
                }
            }
        }
        #pragma unroll
        for (int i = 0; i < 6; i++) {
            uint32_t hi, lo; split_tf32(rw[i], hi, lo);
            Wh[0][wr_ld + i][wco_ld] = hi;
            Wl[0][wr_ld + i][wco_ld] = lo;
        }
    }
    __syncthreads();

    int buf = 0;
    for (int ci0 = 0; ci0 < CH; ci0 += 8) {
        const bool has_next = (ci0 + 8) < CH;

        // ---- issue global loads for next chunk (overlap with MMAs) ----
        if (has_next) {
            const float* xrow = xb + (size_t)(ci0 + 8 + xr) * LEN + (l0 - 1);
            #pragma unroll
            for (int i = 0; i < 5; i++) {
                int c = lane + (i << 5);
                int gl = l0 - 1 + c;
                rx[i] = (c < 130 && gl >= 0 && gl < LEN) ? xrow[c] : 0.f;
            }
            const float* wp = w + (size_t)(co0 + wco_ld) * (CH * 3)
                            + (ci0 + 8) * 3 + wr_ld;
            #pragma unroll
            for (int i = 0; i < 6; i++) rw[i] = wp[i];
        }

        // ---- compute chunk from buf ----
        #pragma unroll
        for (int t = 0; t < 3; t++) {
            uint32_t ah[4], al[4];
            const int r0 = tg * 3 + t;
            ah[0] = Wh[buf][r0     ][wco + g    ]; al[0] = Wl[buf][r0     ][wco + g    ];
            ah[1] = Wh[buf][r0     ][wco + g + 8]; al[1] = Wl[buf][r0     ][wco + g + 8];
            ah[2] = Wh[buf][r0 + 12][wco + g    ]; al[2] = Wl[buf][r0 + 12][wco + g    ];
            ah[3] = Wh[buf][r0 + 12][wco + g + 8]; al[3] = Wl[buf][r0 + 12][wco + g + 8];
            #pragma unroll
            for (int a2 = 0; a2 < 8; a2++) {
                const int c = wpos + (a2 << 3) + g + t;
                uint32_t bh0 = Xh[buf][tg    ][c];
                uint32_t bh1 = Xh[buf][tg + 4][c];
                mma_tf32(acc[a2], ah, bh0, bh1);
                mma_tf32(acc[a2], al, bh0, bh1);
                if (SPLITX) {
                    uint32_t bl0 = Xl[buf][tg    ][c];
                    uint32_t bl1 = Xl[buf][tg + 4][c];
                    mma_tf32(acc[a2], ah, bl0, bl1);
                }
            }
        }

        // ---- convert + store next chunk into the other buffer ----
        if (has_next) {
            const int nb = buf ^ 1;
            #pragma unroll
            for (int i = 0; i < 5; i++) {
                int c = lane + (i << 5);
                if (c < 130) {
                    if (SPLITX) {
                        uint32_t hi, lo; split_tf32(rx[i], hi, lo);
                        Xh[nb][xr][c] = hi; Xl[nb][xr][c] = lo;
                    } else {
                        Xh[nb][xr][c] = tf32_rna(rx[i]);
                    }
                }
            }
            #pragma unroll
            for (int i = 0; i < 6; i++) {
                uint32_t hi, lo; split_tf32(rw[i], hi, lo);
                Wh[nb][wr_ld + i][wco_ld] = hi;
                Wl[nb][wr_ld + i][wco_ld] = lo;
            }
            __syncthreads();
            buf = nb;
        }
    }

    const int row = co0 + wco + g;
    const float bv0 = bias[row], bv1 = bias[row + 8];
    float* y0 = y + ((size_t)b * CH + row) * LEN + l0 + wpos + (tg << 1);
    #pragma unroll
    for (int a2 = 0; a2 < 8; a2++) {
        *(float2*)(y0 + (a2 << 3)) =
            make_float2(acc[a2].x + bv0, acc[a2].y + bv0);
        *(float2*)(y0 + (size_t)8 * LEN + (a2 << 3)) =
            make_float2(acc[a2].z + bv1, acc[a2].w + bv1);
    }
}

__global__ __launch_bounds__(256)
void conv_qkv_k(const float* __restrict__ q, const float* __restrict__ k,
                const float* __restrict__ v,
                const float* __restrict__ wq, const float* __restrict__ wk,
                const float* __restrict__ wv,
                const float* __restrict__ bq, const float* __restrict__ bk,
                const float* __restrict__ bv,
                float* __restrict__ yq, float* __restrict__ yk,
                float* __restrict__ yv)
{
    int sel = blockIdx.z >> 2, b = blockIdx.z & 3;
    const float* x; const float* w; const float* bia; float* y;
    if (sel == 0)      { x = q; w = wq; bia = bq; y = yq; }
    else if (sel == 1) { x = k; w = wk; bia = bk; y = yk; }
    else               { x = v; w = wv; bia = bv; y = yv; }
    conv_body<false>(x, w, bia, y, b, blockIdx.y << 6, blockIdx.x << 7);
}

__global__ __launch_bounds__(256)
void conv1d_k(const float* __restrict__ x, const float* __restrict__ w,
              const float* __restrict__ bias, float* __restrict__ y)
{
    conv_body<true>(x, w, bias, y, blockIdx.z, blockIdx.y << 6, blockIdx.x << 7);
}

// ---------------------------------------------------------------------------
// Flash attention on tensor cores (single-pass tf32).
// Block = (64-query tile, h, b); 128 threads = 4 warps; warp owns 16 rows.
// Torch-faithful reshape: A[b,h,n,d] = conv[b, n>>2, (n&3)*512 + h*64 + d].
// ---------------------------------------------------------------------------
#define KP_PITCH 68
#define V_PITCH  72

__global__ __launch_bounds__(128)
void attn_k(const float* __restrict__ yq, const float* __restrict__ yk,
            const float* __restrict__ yv, float* __restrict__ z)
{
    __shared__ uint32_t KP[64 * KP_PITCH];  // K tf32 [j][d] -> P tf32 [row][j]
    __shared__ uint32_t Vs[64 * V_PITCH];   // V tf32 [j][d]

    const int tid  = threadIdx.x;
    const int lane = tid & 31;
    const int wid  = tid >> 5;
    const int g    = lane >> 2;
    const int tg   = lane & 3;
    const int m0   = wid << 4;

    const int b = blockIdx.z, h = blockIdx.y;
    const int t0 = blockIdx.x << 6;
    const size_t bbase = (size_t)b * (CH * LEN);
    const int hoff = h << 6;

#define AOFF(n) (bbase + (size_t)((n) >> 2) * LEN + ((n) & 3) * 512 + hoff)

    uint32_t qa[8][4];
    {
        const float* q0 = yq + AOFF(t0 + m0 + g);
        const float* q1 = yq + AOFF(t0 + m0 + g + 8);
        #pragma unroll
        for (int kt = 0; kt < 8; kt++) {
            qa[kt][0] = tf32_rna(q0[tg + 8 * kt]);
            qa[kt][1] = tf32_rna(q1[tg + 8 * kt]);
            qa[kt][2] = tf32_rna(q0[tg + 4 + 8 * kt]);
            qa[kt][3] = tf32_rna(q1[tg + 4 + 8 * kt]);
        }
    }

    float mrow[2] = {-INFINITY, -INFINITY};
    float lrow[2] = {0.f, 0.f};
    float4 o[8];
    #pragma unroll
    for (int nt = 0; nt < 8; nt++) o[nt] = make_float4(0.f, 0.f, 0.f, 0.f);

    for (int j0 = 0; j0 < LEN; j0 += 64) {
        __syncthreads();
        for (int i = tid; i < 1024; i += 128) {
            int r = i >> 4, c4 = (i & 15) << 2;
            size_t off = AOFF(j0 + r) + c4;
            float4 kk = *(const float4*)(yk + off);
            float4 vv = *(const float4*)(yv + off);
            uint4 ku = make_uint4(tf32_rna(kk.x), tf32_rna(kk.y),
                                  tf32_rna(kk.z), tf32_rna(kk.w));
            uint4 vu = make_uint4(tf32_rna(vv.x), tf32_rna(vv.y),
                                  tf32_rna(vv.z), tf32_rna(vv.w));
            *(uint4*)&KP[r * KP_PITCH + c4] = ku;
            *(uint4*)&Vs[r * V_PITCH  + c4] = vu;
        }
        __syncthreads();

        float4 sA[8];
        #pragma unroll
        for (int nt = 0; nt < 8; nt++) sA[nt] = make_float4(0.f, 0.f, 0.f, 0.f);
        #pragma unroll
        for (int kt = 0; kt < 8; kt++) {
            #pragma unroll
            for (int nt = 0; nt < 8; nt++) {
                uint32_t b0 = KP[(nt * 8 + g) * KP_PITCH + tg + 8 * kt];
                uint32_t b1 = KP[(nt * 8 + g) * KP_PITCH + tg + 4 + 8 * kt];
                mma_tf32(sA[nt], qa[kt], b0, b1);
            }
        }
        __syncthreads();

        const float scale = 1.f / 64.f;
        float mx0 = -INFINITY, mx1 = -INFINITY;
        #pragma unroll
        for (int nt = 0; nt < 8; nt++) {
            mx0 = fmaxf(mx0, fmaxf(sA[nt].x, sA[nt].y));
            mx1 = fmaxf(mx1, fmaxf(sA[nt].z, sA[nt].w));
        }
        mx0 *= scale; mx1 *= scale;
        mx0 = fmaxf(mx0, __shfl_xor_sync(0xffffffffu, mx0, 1));
        mx0 = fmaxf(mx0, __shfl_xor_sync(0xffffffffu, mx0, 2));
        mx1 = fmaxf(mx1, __shfl_xor_sync(0xffffffffu, mx1, 1));
        mx1 = fmaxf(mx1, __shfl_xor_sync(0xffffffffu, mx1, 2));
        float nm0 = fmaxf(mrow[0], mx0);
        float nm1 = fmaxf(mrow[1], mx1);
        float corr0 = __expf(mrow[0] - nm0);
        float corr1 = __expf(mrow[1] - nm1);
        mrow[0] = nm0; mrow[1] = nm1;

        float rs0 = 0.f, rs1 = 0.f;
        uint32_t* Prow0 = &KP[(m0 + g)     * KP_PITCH + (tg << 1)];
        uint32_t* Prow1 = &KP[(m0 + g + 8) * KP_PITCH + (tg << 1)];
        #pragma unroll
        for (int nt = 0; nt < 8; nt++) {
            float p00 = __expf(sA[nt].x * scale - nm0);
            float p01 = __expf(sA[nt].y * scale - nm0);
            float p10 = __expf(sA[nt].z * scale - nm1);
            float p11 = __expf(sA[nt].w * scale - nm1);
            rs0 += p00 + p01;
            rs1 += p10 + p11;
            Prow0[nt * 8 + 0] = tf32_rna(p00);
            Prow0[nt * 8 + 1] = tf32_rna(p01);
            Prow1[nt * 8 + 0] = tf32_rna(p10);
            Prow1[nt * 8 + 1] = tf32_rna(p11);
            o[nt].x *= corr0; o[nt].y *= corr0;
            o[nt].z *= corr1; o[nt].w *= corr1;
        }
        rs0 += __shfl_xor_sync(0xffffffffu, rs0, 1);
        rs0 += __shfl_xor_sync(0xffffffffu, rs0, 2);
        rs1 += __shfl_xor_sync(0xffffffffu, rs1, 1);
        rs1 += __shfl_xor_sync(0xffffffffu, rs1, 2);
        lrow[0] = lrow[0] * corr0 + rs0;
        lrow[1] = lrow[1] * corr1 + rs1;
        __syncwarp();

        #pragma unroll
        for (int kt = 0; kt < 8; kt++) {
            uint32_t pa[4];
            pa[0] = KP[(m0 + g)     * KP_PITCH + tg + 8 * kt];
            pa[1] = KP[(m0 + g + 8) * KP_PITCH + tg + 8 * kt];
            pa[2] = KP[(m0 + g)     * KP_PITCH + tg + 4 + 8 * kt];
            pa[3] = KP[(m0 + g + 8) * KP_PITCH + tg + 4 + 8 * kt];
            #pragma unroll
            for (int nt = 0; nt < 8; nt++) {
                uint32_t b0 = Vs[(tg + 8 * kt)     * V_PITCH + nt * 8 + g];
                uint32_t b1 = Vs[(tg + 4 + 8 * kt) * V_PITCH + nt * 8 + g];
                mma_tf32(o[nt], pa, b0, b1);
            }
        }
    }

    const float inv0 = 1.f / lrow[0];
    const float inv1 = 1.f / lrow[1];
    float* z0 = z + AOFF(t0 + m0 + g)     + (tg << 1);
    float* z1 = z + AOFF(t0 + m0 + g + 8) + (tg << 1);
    #pragma unroll
    for (int nt = 0; nt < 8; nt++) {
        *(float2*)(z0 + nt * 8) = make_float2(o[nt].x * inv0, o[nt].y * inv0);
        *(float2*)(z1 + nt * 8) = make_float2(o[nt].z * inv1, o[nt].w * inv1);
    }
#undef AOFF
}

// ---------------------------------------------------------------------------
extern "C" void kernel_launch(void* const* d_in, const int* in_sizes, int n_in,
                              void* d_out, int out_size)
{
    const float* q    = (const float*)d_in[0];
    const float* k    = (const float*)d_in[1];
    const float* v    = (const float*)d_in[2];
    const float* wq_w = (const float*)d_in[3];
    const float* wq_b = (const float*)d_in[4];
    const float* wk_w = (const float*)d_in[5];
    const float* wk_b = (const float*)d_in[6];
    const float* wv_w = (const float*)d_in[7];
    const float* wv_b = (const float*)d_in[8];
    const float* fc_w = (const float*)d_in[9];
    const float* fc_b = (const float*)d_in[10];
    float* out = (float*)d_out;

    float *yq, *yk, *yv, *zb;
    cudaGetSymbolAddress((void**)&yq, g_yq);
    cudaGetSymbolAddress((void**)&yk, g_yk);
    cudaGetSymbolAddress((void**)&yv, g_yv);
    cudaGetSymbolAddress((void**)&zb, g_z);

    dim3 gqkv(LEN / 128, CH / 64, 3 * BATCH);   // (16, 8, 12)
    conv_qkv_k<<<gqkv, 256>>>(q, k, v, wq_w, wk_w, wv_w, wq_b, wk_b, wv_b,
                              yq, yk, yv);

    dim3 agrid(LEN / 64, 8, BATCH);             // (32, 8, 4)
    attn_k<<<agrid, 128>>>(yq, yk, yv, zb);

    dim3 gfc(LEN / 128, CH / 64, BATCH);        // (16, 8, 4)
    conv1d_k<<<gfc, 256>>>(zb, fc_w, fc_b, out);
}

// round 8
// speedup vs baseline: 1.0352x; 1.0352x over previous
#include <cuda_runtime.h>
#include <math.h>
#include <stdint.h>

#define BATCH 4
#define CH    512
#define LEN   2048

__device__ float g_yq[BATCH*CH*LEN];
__device__ float g_yk[BATCH*CH*LEN];
__device__ float g_yv[BATCH*CH*LEN];
__device__ float g_z [BATCH*CH*LEN];

// ---- tf32 helpers -----------------------------------------------------------
__device__ __forceinline__ uint32_t tf32_rna(float a) {
    uint32_t r; asm("cvt.rna.tf32.f32 %0, %1;" : "=r"(r) : "f"(a)); return r;
}
__device__ __forceinline__ void split_tf32(float a, uint32_t& hi, uint32_t& lo) {
    hi = tf32_rna(a);
    lo = tf32_rna(a - __uint_as_float(hi));
}
__device__ __forceinline__ void mma_tf32(float4& d, const uint32_t* a,
                                         uint32_t b0, uint32_t b1) {
    asm volatile(
        "mma.sync.aligned.m16n8k8.row.col.f32.tf32.tf32.f32 "
        "{%0,%1,%2,%3},{%4,%5,%6,%7},{%8,%9},{%0,%1,%2,%3};"
        : "+f"(d.x), "+f"(d.y), "+f"(d.z), "+f"(d.w)
        : "r"(a[0]), "r"(a[1]), "r"(a[2]), "r"(a[3]), "r"(b0), "r"(b1));
}

// ---------------------------------------------------------------------------
// Conv1d (k=3, 'same') on tensor cores. Block tile 128co x 128pos, 256 thr
// = 8 warps as 4 co-groups x 2 pos-groups; warp tile 32co x 64pos (2 m-tiles,
// B-fragments reused across both -> 128 B smem traffic per MMA, was 192).
// W split hi/lo always; X split only for fc conv (SPLITX).
// Single smem buffer + register prefetch of the next 8-ci chunk.
// ---------------------------------------------------------------------------
#define WS_PITCH 136   // 136 % 32 == 8 -> A-frag reads conflict-free
#define XS_PITCH 136   // B-frag reads conflict-free

template<bool SPLITX>
__device__ __forceinline__
void conv_body(const float* __restrict__ x, const float* __restrict__ w,
               const float* __restrict__ bias, float* __restrict__ y,
               int b, int co0, int l0)
{
    __shared__ uint32_t Wh[24][WS_PITCH], Wl[24][WS_PITCH];
    __shared__ uint32_t Xh[8][XS_PITCH];
    __shared__ uint32_t Xl[SPLITX ? 8 : 1][XS_PITCH];

    const int tid  = threadIdx.x;
    const int lane = tid & 31;
    const int wid  = tid >> 5;
    const int g    = lane >> 2;       // 0..7
    const int tg   = lane & 3;        // 0..3
    const int wco  = (wid & 3) << 5;  // 0,32,64,96
    const int wpos = (wid >> 2) << 6; // 0,64
    const float* xb = x + (size_t)b * (CH * LEN);

    float4 acc[2][8];
    #pragma unroll
    for (int m = 0; m < 2; m++)
        #pragma unroll
        for (int i = 0; i < 8; i++) acc[m][i] = make_float4(0.f, 0.f, 0.f, 0.f);

    // staging roles
    const int xr     = tid >> 5;        // X row 0..7 (one row per warp)
    const int wco_ld = tid & 127;       // 0..127
    const int wr_ld  = (tid >> 7) * 12; // 0 or 12

    float rx[5], rw[12];

    // ---- prefetch chunk 0 ----
    {
        const float* xrow = xb + (size_t)xr * LEN + (l0 - 1);
        #pragma unroll
        for (int i = 0; i < 5; i++) {
            int c = lane + (i << 5);
            int gl = l0 - 1 + c;
            rx[i] = (c < 130 && gl >= 0 && gl < LEN) ? xrow[c] : 0.f;
        }
        const float* wp = w + (size_t)(co0 + wco_ld) * (CH * 3) + wr_ld;
        #pragma unroll
        for (int i = 0; i < 3; i++) {
            float4 w4 = *(const float4*)(wp + (i << 2));
            rw[i*4+0] = w4.x; rw[i*4+1] = w4.y; rw[i*4+2] = w4.z; rw[i*4+3] = w4.w;
        }
    }

    for (int ci0 = 0; ci0 < CH; ci0 += 8) {
        // ---- store prefetched chunk to smem (tf32 conversion here) ----
        #pragma unroll
        for (int i = 0; i < 5; i++) {
            int c = lane + (i << 5);
            if (c < 130) {
                if (SPLITX) {
                    uint32_t hi, lo; split_tf32(rx[i], hi, lo);
                    Xh[xr][c] = hi; Xl[xr][c] = lo;
                } else {
                    Xh[xr][c] = tf32_rna(rx[i]);
                }
            }
        }
        #pragma unroll
        for (int i = 0; i < 12; i++) {
            uint32_t hi, lo; split_tf32(rw[i], hi, lo);
            Wh[wr_ld + i][wco_ld] = hi;
            Wl[wr_ld + i][wco_ld] = lo;
        }
        __syncthreads();

        // ---- prefetch next chunk into registers (overlaps with MMAs) ----
        if (ci0 + 8 < CH) {
            const float* xrow = xb + (size_t)(ci0 + 8 + xr) * LEN + (l0 - 1);
            #pragma unroll
            for (int i = 0; i < 5; i++) {
                int c = lane + (i << 5);
                int gl = l0 - 1 + c;
                rx[i] = (c < 130 && gl >= 0 && gl < LEN) ? xrow[c] : 0.f;
            }
            const float* wp = w + (size_t)(co0 + wco_ld) * (CH * 3)
                            + (ci0 + 8) * 3 + wr_ld;
            #pragma unroll
            for (int i = 0; i < 3; i++) {
                float4 w4 = *(const float4*)(wp + (i << 2));
                rw[i*4+0] = w4.x; rw[i*4+1] = w4.y; rw[i*4+2] = w4.z; rw[i*4+3] = w4.w;
            }
        }

        // ---- compute chunk from smem ----
        #pragma unroll
        for (int t = 0; t < 3; t++) {
            uint32_t ah[2][4], al[2][4];
            const int r0 = tg * 3 + t;
            #pragma unroll
            for (int m = 0; m < 2; m++) {
                const int cb = wco + (m << 4);
                ah[m][0] = Wh[r0     ][cb + g    ]; al[m][0] = Wl[r0     ][cb + g    ];
                ah[m][1] = Wh[r0     ][cb + g + 8]; al[m][1] = Wl[r0     ][cb + g + 8];
                ah[m][2] = Wh[r0 + 12][cb + g    ]; al[m][2] = Wl[r0 + 12][cb + g    ];
                ah[m][3] = Wh[r0 + 12][cb + g + 8]; al[m][3] = Wl[r0 + 12][cb + g + 8];
            }
            #pragma unroll
            for (int a2 = 0; a2 < 8; a2++) {
                const int c = wpos + (a2 << 3) + g + t;
                uint32_t bh0 = Xh[tg    ][c];
                uint32_t bh1 = Xh[tg + 4][c];
                if (SPLITX) {
                    uint32_t bl0 = Xl[tg    ][c];
                    uint32_t bl1 = Xl[tg + 4][c];
                    #pragma unroll
                    for (int m = 0; m < 2; m++) {
                        mma_tf32(acc[m][a2], ah[m], bh0, bh1);
                        mma_tf32(acc[m][a2], al[m], bh0, bh1);
                        mma_tf32(acc[m][a2], ah[m], bl0, bl1);
                    }
                } else {
                    #pragma unroll
                    for (int m = 0; m < 2; m++) {
                        mma_tf32(acc[m][a2], ah[m], bh0, bh1);
                        mma_tf32(acc[m][a2], al[m], bh0, bh1);
                    }
                }
            }
        }
        __syncthreads();   // done reading before next chunk's stores
    }

    #pragma unroll
    for (int m = 0; m < 2; m++) {
        const int row = co0 + wco + (m << 4) + g;
        const float bv0 = bias[row], bv1 = bias[row + 8];
        float* y0 = y + ((size_t)b * CH + row) * LEN + l0 + wpos + (tg << 1);
        #pragma unroll
        for (int a2 = 0; a2 < 8; a2++) {
            *(float2*)(y0 + (a2 << 3)) =
                make_float2(acc[m][a2].x + bv0, acc[m][a2].y + bv0);
            *(float2*)(y0 + (size_t)8 * LEN + (a2 << 3)) =
                make_float2(acc[m][a2].z + bv1, acc[m][a2].w + bv1);
        }
    }
}

__global__ __launch_bounds__(256)
void conv_qkv_k(const float* __restrict__ q, const float* __restrict__ k,
                const float* __restrict__ v,
                const float* __restrict__ wq, const float* __restrict__ wk,
                const float* __restrict__ wv,
                const float* __restrict__ bq, const float* __restrict__ bk,
                const float* __restrict__ bv,
                float* __restrict__ yq, float* __restrict__ yk,
                float* __restrict__ yv)
{
    int sel = blockIdx.z >> 2, b = blockIdx.z & 3;
    const float* x; const float* w; const float* bia; float* y;
    if (sel == 0)      { x = q; w = wq; bia = bq; y = yq; }
    else if (sel == 1) { x = k; w = wk; bia = bk; y = yk; }
    else               { x = v; w = wv; bia = bv; y = yv; }
    conv_body<false>(x, w, bia, y, b, blockIdx.y << 7, blockIdx.x << 7);
}

__global__ __launch_bounds__(256)
void conv1d_k(const float* __restrict__ x, const float* __restrict__ w,
              const float* __restrict__ bias, float* __restrict__ y)
{
    conv_body<true>(x, w, bias, y, blockIdx.z, blockIdx.y << 7, blockIdx.x << 7);
}

// ---------------------------------------------------------------------------
// Flash attention on tensor cores (single-pass tf32).
// Block = (64-query tile, h, b); 128 threads = 4 warps; warp owns 16 rows.
// Torch-faithful reshape: A[b,h,n,d] = conv[b, n>>2, (n&3)*512 + h*64 + d].
// ---------------------------------------------------------------------------
#define KP_PITCH 68
#define V_PITCH  72

__global__ __launch_bounds__(128)
void attn_k(const float* __restrict__ yq, const float* __restrict__ yk,
            const float* __restrict__ yv, float* __restrict__ z)
{
    __shared__ uint32_t KP[64 * KP_PITCH];  // K tf32 [j][d] -> P tf32 [row][j]
    __shared__ uint32_t Vs[64 * V_PITCH];   // V tf32 [j][d]

    const int tid  = threadIdx.x;
    const int lane = tid & 31;
    const int wid  = tid >> 5;
    const int g    = lane >> 2;
    const int tg   = lane & 3;
    const int m0   = wid << 4;

    const int b = blockIdx.z, h = blockIdx.y;
    const int t0 = blockIdx.x << 6;
    const size_t bbase = (size_t)b * (CH * LEN);
    const int hoff = h << 6;

#define AOFF(n) (bbase + (size_t)((n) >> 2) * LEN + ((n) & 3) * 512 + hoff)

    uint32_t qa[8][4];
    {
        const float* q0 = yq + AOFF(t0 + m0 + g);
        const float* q1 = yq + AOFF(t0 + m0 + g + 8);
        #pragma unroll
        for (int kt = 0; kt < 8; kt++) {
            qa[kt][0] = tf32_rna(q0[tg + 8 * kt]);
            qa[kt][1] = tf32_rna(q1[tg + 8 * kt]);
            qa[kt][2] = tf32_rna(q0[tg + 4 + 8 * kt]);
            qa[kt][3] = tf32_rna(q1[tg + 4 + 8 * kt]);
        }
    }

    float mrow[2] = {-INFINITY, -INFINITY};
    float lrow[2] = {0.f, 0.f};
    float4 o[8];
    #pragma unroll
    for (int nt = 0; nt < 8; nt++) o[nt] = make_float4(0.f, 0.f, 0.f, 0.f);

    for (int j0 = 0; j0 < LEN; j0 += 64) {
        __syncthreads();
        for (int i = tid; i < 1024; i += 128) {
            int r = i >> 4, c4 = (i & 15) << 2;
            size_t off = AOFF(j0 + r) + c4;
            float4 kk = *(const float4*)(yk + off);
            float4 vv = *(const float4*)(yv + off);
            uint4 ku = make_uint4(tf32_rna(kk.x), tf32_rna(kk.y),
                                  tf32_rna(kk.z), tf32_rna(kk.w));
            uint4 vu = make_uint4(tf32_rna(vv.x), tf32_rna(vv.y),
                                  tf32_rna(vv.z), tf32_rna(vv.w));
            *(uint4*)&KP[r * KP_PITCH + c4] = ku;
            *(uint4*)&Vs[r * V_PITCH  + c4] = vu;
        }
        __syncthreads();

        float4 sA[8];
        #pragma unroll
        for (int nt = 0; nt < 8; nt++) sA[nt] = make_float4(0.f, 0.f, 0.f, 0.f);
        #pragma unroll
        for (int kt = 0; kt < 8; kt++) {
            #pragma unroll
            for (int nt = 0; nt < 8; nt++) {
                uint32_t b0 = KP[(nt * 8 + g) * KP_PITCH + tg + 8 * kt];
                uint32_t b1 = KP[(nt * 8 + g) * KP_PITCH + tg + 4 + 8 * kt];
                mma_tf32(sA[nt], qa[kt], b0, b1);
            }
        }
        __syncthreads();

        const float scale = 1.f / 64.f;
        float mx0 = -INFINITY, mx1 = -INFINITY;
        #pragma unroll
        for (int nt = 0; nt < 8; nt++) {
            mx0 = fmaxf(mx0, fmaxf(sA[nt].x, sA[nt].y));
            mx1 = fmaxf(mx1, fmaxf(sA[nt].z, sA[nt].w));
        }
        mx0 *= scale; mx1 *= scale;
        mx0 = fmaxf(mx0, __shfl_xor_sync(0xffffffffu, mx0, 1));
        mx0 = fmaxf(mx0, __shfl_xor_sync(0xffffffffu, mx0, 2));
        mx1 = fmaxf(mx1, __shfl_xor_sync(0xffffffffu, mx1, 1));
        mx1 = fmaxf(mx1, __shfl_xor_sync(0xffffffffu, mx1, 2));
        float nm0 = fmaxf(mrow[0], mx0);
        float nm1 = fmaxf(mrow[1], mx1);
        float corr0 = __expf(mrow[0] - nm0);
        float corr1 = __expf(mrow[1] - nm1);
        mrow[0] = nm0; mrow[1] = nm1;

        float rs0 = 0.f, rs1 = 0.f;
        uint32_t* Prow0 = &KP[(m0 + g)     * KP_PITCH + (tg << 1)];
        uint32_t* Prow1 = &KP[(m0 + g + 8) * KP_PITCH + (tg << 1)];
        #pragma unroll
        for (int nt = 0; nt < 8; nt++) {
            float p00 = __expf(sA[nt].x * scale - nm0);
            float p01 = __expf(sA[nt].y * scale - nm0);
            float p10 = __expf(sA[nt].z * scale - nm1);
            float p11 = __expf(sA[nt].w * scale - nm1);
            rs0 += p00 + p01;
            rs1 += p10 + p11;
            Prow0[nt * 8 + 0] = tf32_rna(p00);
            Prow0[nt * 8 + 1] = tf32_rna(p01);
            Prow1[nt * 8 + 0] = tf32_rna(p10);
            Prow1[nt * 8 + 1] = tf32_rna(p11);
            o[nt].x *= corr0; o[nt].y *= corr0;
            o[nt].z *= corr1; o[nt].w *= corr1;
        }
        rs0 += __shfl_xor_sync(0xffffffffu, rs0, 1);
        rs0 += __shfl_xor_sync(0xffffffffu, rs0, 2);
        rs1 += __shfl_xor_sync(0xffffffffu, rs1, 1);
        rs1 += __shfl_xor_sync(0xffffffffu, rs1, 2);
        lrow[0] = lrow[0] * corr0 + rs0;
        lrow[1] = lrow[1] * corr1 + rs1;
        __syncwarp();

        #pragma unroll
        for (int kt = 0; kt < 8; kt++) {
            uint32_t pa[4];
            pa[0] = KP[(m0 + g)     * KP_PITCH + tg + 8 * kt];
            pa[1] = KP[(m0 + g + 8) * KP_PITCH + tg + 8 * kt];
            pa[2] = KP[(m0 + g)     * KP_PITCH + tg + 4 + 8 * kt];
            pa[3] = KP[(m0 + g + 8) * KP_PITCH + tg + 4 + 8 * kt];
            #pragma unroll
            for (int nt = 0; nt < 8; nt++) {
                uint32_t b0 = Vs[(tg + 8 * kt)     * V_PITCH + nt * 8 + g];
                uint32_t b1 = Vs[(tg + 4 + 8 * kt) * V_PITCH + nt * 8 + g];
                mma_tf32(o[nt], pa, b0, b1);
            }
        }
    }

    const float inv0 = 1.f / lrow[0];
    const float inv1 = 1.f / lrow[1];
    float* z0 = z + AOFF(t0 + m0 + g)     + (tg << 1);
    float* z1 = z + AOFF(t0 + m0 + g + 8) + (tg << 1);
    #pragma unroll
    for (int nt = 0; nt < 8; nt++) {
        *(float2*)(z0 + nt * 8) = make_float2(o[nt].x * inv0, o[nt].y * inv0);
        *(float2*)(z1 + nt * 8) = make_float2(o[nt].z * inv1, o[nt].w * inv1);
    }
#undef AOFF
}

// ---------------------------------------------------------------------------
extern "C" void kernel_launch(void* const* d_in, const int* in_sizes, int n_in,
                              void* d_out, int out_size)
{
    const float* q    = (const float*)d_in[0];
    const float* k    = (const float*)d_in[1];
    const float* v    = (const float*)d_in[2];
    const float* wq_w = (const float*)d_in[3];
    const float* wq_b = (const float*)d_in[4];
    const float* wk_w = (const float*)d_in[5];
    const float* wk_b = (const float*)d_in[6];
    const float* wv_w = (const float*)d_in[7];
    const float* wv_b = (const float*)d_in[8];
    const float* fc_w = (const float*)d_in[9];
    const float* fc_b = (const float*)d_in[10];
    float* out = (float*)d_out;

    float *yq, *yk, *yv, *zb;
    cudaGetSymbolAddress((void**)&yq, g_yq);
    cudaGetSymbolAddress((void**)&yk, g_yk);
    cudaGetSymbolAddress((void**)&yv, g_yv);
    cudaGetSymbolAddress((void**)&zb, g_z);

    dim3 gqkv(LEN / 128, CH / 128, 3 * BATCH);  // (16, 4, 12)
    conv_qkv_k<<<gqkv, 256>>>(q, k, v, wq_w, wk_w, wv_w, wq_b, wk_b, wv_b,
                              yq, yk, yv);

    dim3 agrid(LEN / 64, 8, BATCH);             // (32, 8, 4)
    attn_k<<<agrid, 128>>>(yq, yk, yv, zb);

    dim3 gfc(LEN / 128, CH / 128, BATCH);       // (16, 4, 4)
    conv1d_k<<<gfc, 256>>>(zb, fc_w, fc_b, out);
}

// round 9
// speedup vs baseline: 1.3054x; 1.2609x over previous
#include <cuda_runtime.h>
#include <math.h>
#include <stdint.h>

#define BATCH 4
#define CH    512
#define LEN   2048

__device__ float g_yq[BATCH*CH*LEN];
__device__ float g_yk[BATCH*CH*LEN];
__device__ float g_yv[BATCH*CH*LEN];
__device__ float g_z [BATCH*CH*LEN];

// ---- tf32 helpers -----------------------------------------------------------
__device__ __forceinline__ uint32_t tf32_rna(float a) {
    uint32_t r; asm("cvt.rna.tf32.f32 %0, %1;" : "=r"(r) : "f"(a)); return r;
}
__device__ __forceinline__ void split_tf32(float a, uint32_t& hi, uint32_t& lo) {
    hi = tf32_rna(a);
    lo = tf32_rna(a - __uint_as_float(hi));
}
__device__ __forceinline__ void mma_tf32(float4& d, const uint32_t* a,
                                         uint32_t b0, uint32_t b1) {
    asm volatile(
        "mma.sync.aligned.m16n8k8.row.col.f32.tf32.tf32.f32 "
        "{%0,%1,%2,%3},{%4,%5,%6,%7},{%8,%9},{%0,%1,%2,%3};"
        : "+f"(d.x), "+f"(d.y), "+f"(d.z), "+f"(d.w)
        : "r"(a[0]), "r"(a[1]), "r"(a[2]), "r"(a[3]), "r"(b0), "r"(b1));
}

// ---------------------------------------------------------------------------
// Conv1d (k=3, 'same') on tensor cores. Block tile 128co x 128pos, 256 thr
// = 8 warps (4 co-groups x 2 pos-groups); warp tile 32co x 64pos.
// QKV convs (WSPLIT=false): single-pass tf32 (1 MMA / k-step).
// fc conv  (WSPLIT=true):   2-pass W hi/lo split (X single-pass).
// Single smem buffer + register prefetch of the next 8-ci chunk.
// ---------------------------------------------------------------------------
#define WS_PITCH 136   // 136 % 32 == 8 -> A-frag reads conflict-free
#define XS_PITCH 136   // B-frag reads conflict-free

template<bool WSPLIT>
__device__ __forceinline__
void conv_body(const float* __restrict__ x, const float* __restrict__ w,
               const float* __restrict__ bias, float* __restrict__ y,
               int b, int co0, int l0)
{
    __shared__ uint32_t Wh[24][WS_PITCH];
    __shared__ uint32_t Wl[WSPLIT ? 24 : 1][WS_PITCH];
    __shared__ uint32_t Xh[8][XS_PITCH];

    const int tid  = threadIdx.x;
    const int lane = tid & 31;
    const int wid  = tid >> 5;
    const int g    = lane >> 2;       // 0..7
    const int tg   = lane & 3;        // 0..3
    const int wco  = (wid & 3) << 5;  // 0,32,64,96
    const int wpos = (wid >> 2) << 6; // 0,64
    const float* xb = x + (size_t)b * (CH * LEN);

    float4 acc[2][8];
    #pragma unroll
    for (int m = 0; m < 2; m++)
        #pragma unroll
        for (int i = 0; i < 8; i++) acc[m][i] = make_float4(0.f, 0.f, 0.f, 0.f);

    // staging roles
    const int xr     = tid >> 5;        // X row 0..7 (one row per warp)
    const int wco_ld = tid & 127;       // 0..127
    const int wr_ld  = (tid >> 7) * 12; // 0 or 12

    float rx[5], rw[12];

    // ---- prefetch chunk 0 ----
    {
        const float* xrow = xb + (size_t)xr * LEN + (l0 - 1);
        #pragma unroll
        for (int i = 0; i < 5; i++) {
            int c = lane + (i << 5);
            int gl = l0 - 1 + c;
            rx[i] = (c < 130 && gl >= 0 && gl < LEN) ? xrow[c] : 0.f;
        }
        const float* wp = w + (size_t)(co0 + wco_ld) * (CH * 3) + wr_ld;
        #pragma unroll
        for (int i = 0; i < 3; i++) {
            float4 w4 = *(const float4*)(wp + (i << 2));
            rw[i*4+0] = w4.x; rw[i*4+1] = w4.y; rw[i*4+2] = w4.z; rw[i*4+3] = w4.w;
        }
    }

    for (int ci0 = 0; ci0 < CH; ci0 += 8) {
        // ---- store prefetched chunk to smem (tf32 conversion here) ----
        #pragma unroll
        for (int i = 0; i < 5; i++) {
            int c = lane + (i << 5);
            if (c < 130) Xh[xr][c] = tf32_rna(rx[i]);
        }
        #pragma unroll
        for (int i = 0; i < 12; i++) {
            if (WSPLIT) {
                uint32_t hi, lo; split_tf32(rw[i], hi, lo);
                Wh[wr_ld + i][wco_ld] = hi;
                Wl[wr_ld + i][wco_ld] = lo;
            } else {
                Wh[wr_ld + i][wco_ld] = tf32_rna(rw[i]);
            }
        }
        __syncthreads();

        // ---- prefetch next chunk into registers (overlaps with MMAs) ----
        if (ci0 + 8 < CH) {
            const float* xrow = xb + (size_t)(ci0 + 8 + xr) * LEN + (l0 - 1);
            #pragma unroll
            for (int i = 0; i < 5; i++) {
                int c = lane + (i << 5);
                int gl = l0 - 1 + c;
                rx[i] = (c < 130 && gl >= 0 && gl < LEN) ? xrow[c] : 0.f;
            }
            const float* wp = w + (size_t)(co0 + wco_ld) * (CH * 3)
                            + (ci0 + 8) * 3 + wr_ld;
            #pragma unroll
            for (int i = 0; i < 3; i++) {
                float4 w4 = *(const float4*)(wp + (i << 2));
                rw[i*4+0] = w4.x; rw[i*4+1] = w4.y; rw[i*4+2] = w4.z; rw[i*4+3] = w4.w;
            }
        }

        // ---- compute chunk from smem ----
        #pragma unroll
        for (int t = 0; t < 3; t++) {
            uint32_t ah[2][4], al[2][4];
            const int r0 = tg * 3 + t;
            #pragma unroll
            for (int m = 0; m < 2; m++) {
                const int cb = wco + (m << 4);
                ah[m][0] = Wh[r0     ][cb + g    ];
                ah[m][1] = Wh[r0     ][cb + g + 8];
                ah[m][2] = Wh[r0 + 12][cb + g    ];
                ah[m][3] = Wh[r0 + 12][cb + g + 8];
                if (WSPLIT) {
                    al[m][0] = Wl[r0     ][cb + g    ];
                    al[m][1] = Wl[r0     ][cb + g + 8];
                    al[m][2] = Wl[r0 + 12][cb + g    ];
                    al[m][3] = Wl[r0 + 12][cb + g + 8];
                }
            }
            #pragma unroll
            for (int a2 = 0; a2 < 8; a2++) {
                const int c = wpos + (a2 << 3) + g + t;
                uint32_t bh0 = Xh[tg    ][c];
                uint32_t bh1 = Xh[tg + 4][c];
                #pragma unroll
                for (int m = 0; m < 2; m++) {
                    mma_tf32(acc[m][a2], ah[m], bh0, bh1);
                    if (WSPLIT) mma_tf32(acc[m][a2], al[m], bh0, bh1);
                }
            }
        }
        __syncthreads();   // done reading before next chunk's stores
    }

    #pragma unroll
    for (int m = 0; m < 2; m++) {
        const int row = co0 + wco + (m << 4) + g;
        const float bv0 = bias[row], bv1 = bias[row + 8];
        float* y0 = y + ((size_t)b * CH + row) * LEN + l0 + wpos + (tg << 1);
        #pragma unroll
        for (int a2 = 0; a2 < 8; a2++) {
            *(float2*)(y0 + (a2 << 3)) =
                make_float2(acc[m][a2].x + bv0, acc[m][a2].y + bv0);
            *(float2*)(y0 + (size_t)8 * LEN + (a2 << 3)) =
                make_float2(acc[m][a2].z + bv1, acc[m][a2].w + bv1);
        }
    }
}

__global__ __launch_bounds__(256)
void conv_qkv_k(const float* __restrict__ q, const float* __restrict__ k,
                const float* __restrict__ v,
                const float* __restrict__ wq, const float* __restrict__ wk,
                const float* __restrict__ wv,
                const float* __restrict__ bq, const float* __restrict__ bk,
                const float* __restrict__ bv,
                float* __restrict__ yq, float* __restrict__ yk,
                float* __restrict__ yv)
{
    int sel = blockIdx.z >> 2, b = blockIdx.z & 3;
    const float* x; const float* w; const float* bia; float* y;
    if (sel == 0)      { x = q; w = wq; bia = bq; y = yq; }
    else if (sel == 1) { x = k; w = wk; bia = bk; y = yk; }
    else               { x = v; w = wv; bia = bv; y = yv; }
    conv_body<false>(x, w, bia, y, b, blockIdx.y << 7, blockIdx.x << 7);
}

__global__ __launch_bounds__(256)
void conv1d_k(const float* __restrict__ x, const float* __restrict__ w,
              const float* __restrict__ bias, float* __restrict__ y)
{
    conv_body<true>(x, w, bias, y, blockIdx.z, blockIdx.y << 7, blockIdx.x << 7);
}

// ---------------------------------------------------------------------------
// Flash attention on tensor cores (single-pass tf32).
// Block = (64-query tile, h, b); 128 threads = 4 warps; warp owns 16 rows.
// Torch-faithful reshape: A[b,h,n,d] = conv[b, n>>2, (n&3)*512 + h*64 + d].
// ---------------------------------------------------------------------------
#define KP_PITCH 68
#define V_PITCH  72

__global__ __launch_bounds__(128)
void attn_k(const float* __restrict__ yq, const float* __restrict__ yk,
            const float* __restrict__ yv, float* __restrict__ z)
{
    __shared__ uint32_t KP[64 * KP_PITCH];  // K tf32 [j][d] -> P tf32 [row][j]
    __shared__ uint32_t Vs[64 * V_PITCH];   // V tf32 [j][d]

    const int tid  = threadIdx.x;
    const int lane = tid & 31;
    const int wid  = tid >> 5;
    const int g    = lane >> 2;
    const int tg   = lane & 3;
    const int m0   = wid << 4;

    const int b = blockIdx.z, h = blockIdx.y;
    const int t0 = blockIdx.x << 6;
    const size_t bbase = (size_t)b * (CH * LEN);
    const int hoff = h << 6;

#define AOFF(n) (bbase + (size_t)((n) >> 2) * LEN + ((n) & 3) * 512 + hoff)

    uint32_t qa[8][4];
    {
        const float* q0 = yq + AOFF(t0 + m0 + g);
        const float* q1 = yq + AOFF(t0 + m0 + g + 8);
        #pragma unroll
        for (int kt = 0; kt < 8; kt++) {
            qa[kt][0] = tf32_rna(q0[tg + 8 * kt]);
            qa[kt][1] = tf32_rna(q1[tg + 8 * kt]);
            qa[kt][2] = tf32_rna(q0[tg + 4 + 8 * kt]);
            qa[kt][3] = tf32_rna(q1[tg + 4 + 8 * kt]);
        }
    }

    float mrow[2] = {-INFINITY, -INFINITY};
    float lrow[2] = {0.f, 0.f};
    float4 o[8];
    #pragma unroll
    for (int nt = 0; nt < 8; nt++) o[nt] = make_float4(0.f, 0.f, 0.f, 0.f);

    for (int j0 = 0; j0 < LEN; j0 += 64) {
        __syncthreads();
        for (int i = tid; i < 1024; i += 128) {
            int r = i >> 4, c4 = (i & 15) << 2;
            size_t off = AOFF(j0 + r) + c4;
            float4 kk = *(const float4*)(yk + off);
            float4 vv = *(const float4*)(yv + off);
            uint4 ku = make_uint4(tf32_rna(kk.x), tf32_rna(kk.y),
                                  tf32_rna(kk.z), tf32_rna(kk.w));
            uint4 vu = make_uint4(tf32_rna(vv.x), tf32_rna(vv.y),
                                  tf32_rna(vv.z), tf32_rna(vv.w));
            *(uint4*)&KP[r * KP_PITCH + c4] = ku;
            *(uint4*)&Vs[r * V_PITCH  + c4] = vu;
        }
        __syncthreads();

        float4 sA[8];
        #pragma unroll
        for (int nt = 0; nt < 8; nt++) sA[nt] = make_float4(0.f, 0.f, 0.f, 0.f);
        #pragma unroll
        for (int kt = 0; kt < 8; kt++) {
            #pragma unroll
            for (int nt = 0; nt < 8; nt++) {
                uint32_t b0 = KP[(nt * 8 + g) * KP_PITCH + tg + 8 * kt];
                uint32_t b1 = KP[(nt * 8 + g) * KP_PITCH + tg + 4 + 8 * kt];
                mma_tf32(sA[nt], qa[kt], b0, b1);
            }
        }
        __syncthreads();

        const float scale = 1.f / 64.f;
        float mx0 = -INFINITY, mx1 = -INFINITY;
        #pragma unroll
        for (int nt = 0; nt < 8; nt++) {
            mx0 = fmaxf(mx0, fmaxf(sA[nt].x, sA[nt].y));
            mx1 = fmaxf(mx1, fmaxf(sA[nt].z, sA[nt].w));
        }
        mx0 *= scale; mx1 *= scale;
        mx0 = fmaxf(mx0, __shfl_xor_sync(0xffffffffu, mx0, 1));
        mx0 = fmaxf(mx0, __shfl_xor_sync(0xffffffffu, mx0, 2));
        mx1 = fmaxf(mx1, __shfl_xor_sync(0xffffffffu, mx1, 1));
        mx1 = fmaxf(mx1, __shfl_xor_sync(0xffffffffu, mx1, 2));
        float nm0 = fmaxf(mrow[0], mx0);
        float nm1 = fmaxf(mrow[1], mx1);
        float corr0 = __expf(mrow[0] - nm0);
        float corr1 = __expf(mrow[1] - nm1);
        mrow[0] = nm0; mrow[1] = nm1;

        float rs0 = 0.f, rs1 = 0.f;
        uint32_t* Prow0 = &KP[(m0 + g)     * KP_PITCH + (tg << 1)];
        uint32_t* Prow1 = &KP[(m0 + g + 8) * KP_PITCH + (tg << 1)];
        #pragma unroll
        for (int nt = 0; nt < 8; nt++) {
            float p00 = __expf(sA[nt].x * scale - nm0);
            float p01 = __expf(sA[nt].y * scale - nm0);
            float p10 = __expf(sA[nt].z * scale - nm1);
            float p11 = __expf(sA[nt].w * scale - nm1);
            rs0 += p00 + p01;
            rs1 += p10 + p11;
            Prow0[nt * 8 + 0] = tf32_rna(p00);
            Prow0[nt * 8 + 1] = tf32_rna(p01);
            Prow1[nt * 8 + 0] = tf32_rna(p10);
            Prow1[nt * 8 + 1] = tf32_rna(p11);
            o[nt].x *= corr0; o[nt].y *= corr0;
            o[nt].z *= corr1; o[nt].w *= corr1;
        }
        rs0 += __shfl_xor_sync(0xffffffffu, rs0, 1);
        rs0 += __shfl_xor_sync(0xffffffffu, rs0, 2);
        rs1 += __shfl_xor_sync(0xffffffffu, rs1, 1);
        rs1 += __shfl_xor_sync(0xffffffffu, rs1, 2);
        lrow[0] = lrow[0] * corr0 + rs0;
        lrow[1] = lrow[1] * corr1 + rs1;
        __syncwarp();

        #pragma unroll
        for (int kt = 0; kt < 8; kt++) {
            uint32_t pa[4];
            pa[0] = KP[(m0 + g)     * KP_PITCH + tg + 8 * kt];
            pa[1] = KP[(m0 + g + 8) * KP_PITCH + tg + 8 * kt];
            pa[2] = KP[(m0 + g)     * KP_PITCH + tg + 4 + 8 * kt];
            pa[3] = KP[(m0 + g + 8) * KP_PITCH + tg + 4 + 8 * kt];
            #pragma unroll
            for (int nt = 0; nt < 8; nt++) {
                uint32_t b0 = Vs[(tg + 8 * kt)     * V_PITCH + nt * 8 + g];
                uint32_t b1 = Vs[(tg + 4 + 8 * kt) * V_PITCH + nt * 8 + g];
                mma_tf32(o[nt], pa, b0, b1);
            }
        }
    }

    const float inv0 = 1.f / lrow[0];
    const float inv1 = 1.f / lrow[1];
    float* z0 = z + AOFF(t0 + m0 + g)     + (tg << 1);
    float* z1 = z + AOFF(t0 + m0 + g + 8) + (tg << 1);
    #pragma unroll
    for (int nt = 0; nt < 8; nt++) {
        *(float2*)(z0 + nt * 8) = make_float2(o[nt].x * inv0, o[nt].y * inv0);
        *(float2*)(z1 + nt * 8) = make_float2(o[nt].z * inv1, o[nt].w * inv1);
    }
#undef AOFF
}

// ---------------------------------------------------------------------------
extern "C" void kernel_launch(void* const* d_in, const int* in_sizes, int n_in,
                              void* d_out, int out_size)
{
    const float* q    = (const float*)d_in[0];
    const float* k    = (const float*)d_in[1];
    const float* v    = (const float*)d_in[2];
    const float* wq_w = (const float*)d_in[3];
    const float* wq_b = (const float*)d_in[4];
    const float* wk_w = (const float*)d_in[5];
    const float* wk_b = (const float*)d_in[6];
    const float* wv_w = (const float*)d_in[7];
    const float* wv_b = (const float*)d_in[8];
    const float* fc_w = (const float*)d_in[9];
    const float* fc_b = (const float*)d_in[10];
    float* out = (float*)d_out;

    float *yq, *yk, *yv, *zb;
    cudaGetSymbolAddress((void**)&yq, g_yq);
    cudaGetSymbolAddress((void**)&yk, g_yk);
    cudaGetSymbolAddress((void**)&yv, g_yv);
    cudaGetSymbolAddress((void**)&zb, g_z);

    dim3 gqkv(LEN / 128, CH / 128, 3 * BATCH);  // (16, 4, 12)
    conv_qkv_k<<<gqkv, 256>>>(q, k, v, wq_w, wk_w, wv_w, wq_b, wk_b, wv_b,
                              yq, yk, yv);

    dim3 agrid(LEN / 64, 8, BATCH);             // (32, 8, 4)
    attn_k<<<agrid, 128>>>(yq, yk, yv, zb);

    dim3 gfc(LEN / 128, CH / 128, BATCH);       // (16, 4, 4)
    conv1d_k<<<gfc, 256>>>(zb, fc_w, fc_b, out);
}